// round 1
// baseline (speedup 1.0000x reference)
#include <cuda_runtime.h>
#include <math.h>
#include <stdint.h>

#define BATCH 4
#define SEQ   1024
#define DM    1024
#define NH    16
#define HD    64
#define BH    (BATCH*NH)

// Scratch (device globals: allocation-free per harness rules)
__device__ float g_Qh [BATCH*NH*SEQ*HD];        // [B,H,S,hd]
__device__ float g_Kh [BATCH*NH*SEQ*HD];        // [B,H,S,hd]
__device__ float g_VhT[BATCH*NH*HD*SEQ];        // [B,H,hd,S]
__device__ float g_S  [(size_t)BH*SEQ*SEQ];     // [BH,S,S] scores/probs (268MB)
__device__ float g_AO [BATCH*SEQ*DM];           // [B,S,D] attn out (permuted)
__device__ float g_PE [SEQ*HD];                 // sinusoidal PE table

// ---------------------------------------------------------------------------
// PE table:  pe[s, 2i] = sin(s * e^{-2i*ln(10000)/64}),  pe[s, 2i+1] = cos(...)
// ---------------------------------------------------------------------------
__global__ void pe_init_kernel() {
    int idx = blockIdx.x * blockDim.x + threadIdx.x;   // 65536 total
    if (idx >= SEQ * HD) return;
    int s = idx >> 6;
    int d = idx & 63;
    int de = d & ~1;
    float div = expf(-(float)de * 0.14391156831212787f);   // ln(10000)/64
    float ang = (float)s * div;
    g_PE[idx] = (d & 1) ? cosf(ang) : sinf(ang);
}

// ---------------------------------------------------------------------------
// tf32 helpers
// ---------------------------------------------------------------------------
__device__ __forceinline__ uint32_t f2tf32(float x) {
    uint32_t r;
    asm("cvt.rna.tf32.f32 %0, %1;" : "=r"(r) : "f"(x));
    return r;
}

__device__ __forceinline__ void mma8(float* c, const uint32_t* a, const uint32_t* b) {
    asm volatile(
        "mma.sync.aligned.m16n8k8.row.col.f32.tf32.tf32.f32 "
        "{%0,%1,%2,%3},{%4,%5,%6,%7},{%8,%9},{%0,%1,%2,%3};"
        : "+f"(c[0]), "+f"(c[1]), "+f"(c[2]), "+f"(c[3])
        : "r"(a[0]), "r"(a[1]), "r"(a[2]), "r"(a[3]), "r"(b[0]), "r"(b[1]));
}

// ---------------------------------------------------------------------------
// Epilogue store dispatch
//   EPI 0: Q proj  -> g_Qh  (+bias +PE, permute [B,H,S,hd])
//   EPI 1: K proj  -> g_Kh  (+bias +PE, permute)
//   EPI 2: V proj  -> g_VhT (+bias, permute transposed [B,H,hd,S])
//   EPI 3: scores  -> g_S   (*scale)
//   EPI 4: P @ V   -> g_AO  (permute to [B,S,D])
//   EPI 5: O proj  -> out   (+bias, row-major)
// ---------------------------------------------------------------------------
template<int EPI>
__device__ __forceinline__ void store_elem(int m, int n, int z, float v,
                                           float* __restrict__ Cex,
                                           const float* __restrict__ bias) {
    if constexpr (EPI == 0 || EPI == 1) {
        int b = m >> 10, s = m & 1023, h = n >> 6, d = n & 63;
        v += bias[n] + g_PE[(s << 6) + d];
        float* dst = (EPI == 0) ? g_Qh : g_Kh;
        dst[((size_t)((b * NH + h) * SEQ + s)) * HD + d] = v;
    } else if constexpr (EPI == 2) {
        int b = m >> 10, s = m & 1023, h = n >> 6, d = n & 63;
        v += bias[n];
        g_VhT[((size_t)((b * NH + h) * HD + d)) * SEQ + s] = v;
    } else if constexpr (EPI == 3) {
        v *= 0.125f;  // hd^-0.5
        g_S[(size_t)z * SEQ * SEQ + (size_t)m * SEQ + n] = v;
    } else if constexpr (EPI == 4) {
        int b = z >> 4, h = z & 15;
        g_AO[((size_t)(b * SEQ + m)) * DM + h * HD + n] = v;
    } else {
        v += bias[n];
        Cex[(size_t)m * DM + n] = v;
    }
}

// ---------------------------------------------------------------------------
// NT GEMM: C[M,N] = A[M,K] @ B[N,K]^T   (tf32 tensor cores, fp32 accum)
// CTA tile 128x64, K-chunk 16, 256 threads, 8 warps as 4(m) x 2(n), warp 32x32
// ---------------------------------------------------------------------------
#define BM 128
#define BN 64
#define KC 16
#define KPAD 20

template<int EPI>
__global__ __launch_bounds__(256)
void gemm_kernel(const float* __restrict__ Aex, const float* __restrict__ Bex,
                 float* __restrict__ Cex, const float* __restrict__ bias) {
    constexpr int K  = (EPI == 3) ? 64 : 1024;
    constexpr int KT = K / KC;

    const int z = blockIdx.z;

    const float* A;
    const float* B;
    if constexpr (EPI <= 2)      { A = Aex;                            B = Bex; }
    else if constexpr (EPI == 3) { A = g_Qh + (size_t)z * SEQ * HD;    B = g_Kh  + (size_t)z * SEQ * HD; }
    else if constexpr (EPI == 4) { A = g_S  + (size_t)z * SEQ * SEQ;   B = g_VhT + (size_t)z * HD * SEQ; }
    else                         { A = g_AO;                           B = Bex; }

    __shared__ float As[2][BM][KPAD];
    __shared__ float Bs[2][BN][KPAD];

    const int tid = threadIdx.x;
    const int cm = blockIdx.x * BM;
    const int cn = blockIdx.y * BN;

    // Global load mapping: 4 threads per row of 16 floats
    const int arow = tid >> 2;          // 0..63
    const int acol = (tid & 3) * 4;     // 0,4,8,12
    const float* Aptr0 = A + (size_t)(cm + arow)      * K + acol;
    const float* Aptr1 = A + (size_t)(cm + arow + 64) * K + acol;
    const float* Bptr  = B + (size_t)(cn + arow)      * K + acol;

    const int wid  = tid >> 5;
    const int lane = tid & 31;
    const int wm   = (wid & 3) * 32;
    const int wn   = (wid >> 2) * 32;
    const int gid  = lane >> 2;
    const int tg   = lane & 3;

    float acc[2][4][4];
#pragma unroll
    for (int i = 0; i < 2; i++)
#pragma unroll
        for (int j = 0; j < 4; j++)
#pragma unroll
            for (int l = 0; l < 4; l++) acc[i][j][l] = 0.f;

    // Prologue: load tile 0
    {
        float4 a0 = *(const float4*)(Aptr0);
        float4 a1 = *(const float4*)(Aptr1);
        float4 b0 = *(const float4*)(Bptr);
        As[0][arow     ][acol+0] = __uint_as_float(f2tf32(a0.x));
        As[0][arow     ][acol+1] = __uint_as_float(f2tf32(a0.y));
        As[0][arow     ][acol+2] = __uint_as_float(f2tf32(a0.z));
        As[0][arow     ][acol+3] = __uint_as_float(f2tf32(a0.w));
        As[0][arow + 64][acol+0] = __uint_as_float(f2tf32(a1.x));
        As[0][arow + 64][acol+1] = __uint_as_float(f2tf32(a1.y));
        As[0][arow + 64][acol+2] = __uint_as_float(f2tf32(a1.z));
        As[0][arow + 64][acol+3] = __uint_as_float(f2tf32(a1.w));
        Bs[0][arow][acol+0] = __uint_as_float(f2tf32(b0.x));
        Bs[0][arow][acol+1] = __uint_as_float(f2tf32(b0.y));
        Bs[0][arow][acol+2] = __uint_as_float(f2tf32(b0.z));
        Bs[0][arow][acol+3] = __uint_as_float(f2tf32(b0.w));
    }
    __syncthreads();

    for (int kt = 0; kt < KT; kt++) {
        const int buf = kt & 1;
        float4 ra0, ra1, rb0;
        const bool pf = (kt + 1 < KT);
        if (pf) {
            ra0 = *(const float4*)(Aptr0 + (kt + 1) * KC);
            ra1 = *(const float4*)(Aptr1 + (kt + 1) * KC);
            rb0 = *(const float4*)(Bptr  + (kt + 1) * KC);
        }

        // Compute on smem[buf]
#pragma unroll
        for (int k8 = 0; k8 < KC; k8 += 8) {
            uint32_t af[2][4], bf[4][2];
#pragma unroll
            for (int im = 0; im < 2; im++) {
                int m = wm + im * 16 + gid;
                af[im][0] = __float_as_uint(As[buf][m    ][k8 + tg]);
                af[im][1] = __float_as_uint(As[buf][m + 8][k8 + tg]);
                af[im][2] = __float_as_uint(As[buf][m    ][k8 + tg + 4]);
                af[im][3] = __float_as_uint(As[buf][m + 8][k8 + tg + 4]);
            }
#pragma unroll
            for (int in_ = 0; in_ < 4; in_++) {
                int n = wn + in_ * 8 + gid;
                bf[in_][0] = __float_as_uint(Bs[buf][n][k8 + tg]);
                bf[in_][1] = __float_as_uint(Bs[buf][n][k8 + tg + 4]);
            }
#pragma unroll
            for (int im = 0; im < 2; im++)
#pragma unroll
                for (int in_ = 0; in_ < 4; in_++)
                    mma8(acc[im][in_], af[im], bf[in_]);
        }

        if (pf) {
            const int nb = buf ^ 1;
            As[nb][arow     ][acol+0] = __uint_as_float(f2tf32(ra0.x));
            As[nb][arow     ][acol+1] = __uint_as_float(f2tf32(ra0.y));
            As[nb][arow     ][acol+2] = __uint_as_float(f2tf32(ra0.z));
            As[nb][arow     ][acol+3] = __uint_as_float(f2tf32(ra0.w));
            As[nb][arow + 64][acol+0] = __uint_as_float(f2tf32(ra1.x));
            As[nb][arow + 64][acol+1] = __uint_as_float(f2tf32(ra1.y));
            As[nb][arow + 64][acol+2] = __uint_as_float(f2tf32(ra1.z));
            As[nb][arow + 64][acol+3] = __uint_as_float(f2tf32(ra1.w));
            Bs[nb][arow][acol+0] = __uint_as_float(f2tf32(rb0.x));
            Bs[nb][arow][acol+1] = __uint_as_float(f2tf32(rb0.y));
            Bs[nb][arow][acol+2] = __uint_as_float(f2tf32(rb0.z));
            Bs[nb][arow][acol+3] = __uint_as_float(f2tf32(rb0.w));
        }
        __syncthreads();
    }

    // Epilogue
#pragma unroll
    for (int im = 0; im < 2; im++) {
#pragma unroll
        for (int in_ = 0; in_ < 4; in_++) {
            int r0 = cm + wm + im * 16 + gid;
            int c0 = cn + wn + in_ * 8 + tg * 2;
            store_elem<EPI>(r0,     c0,     z, acc[im][in_][0], Cex, bias);
            store_elem<EPI>(r0,     c0 + 1, z, acc[im][in_][1], Cex, bias);
            store_elem<EPI>(r0 + 8, c0,     z, acc[im][in_][2], Cex, bias);
            store_elem<EPI>(r0 + 8, c0 + 1, z, acc[im][in_][3], Cex, bias);
        }
    }
}

// ---------------------------------------------------------------------------
// Row softmax over g_S: 65536 rows of length 1024. One 256-thread block/row.
// ---------------------------------------------------------------------------
__global__ __launch_bounds__(256)
void softmax_kernel() {
    const size_t row = blockIdx.x;
    float* p = g_S + row * SEQ;
    const int tid = threadIdx.x;

    float4 x = *(float4*)(p + tid * 4);

    float mx = fmaxf(fmaxf(x.x, x.y), fmaxf(x.z, x.w));
#pragma unroll
    for (int o = 16; o; o >>= 1) mx = fmaxf(mx, __shfl_xor_sync(0xffffffffu, mx, o));

    __shared__ float smx[8];
    __shared__ float ssum[8];
    if ((tid & 31) == 0) smx[tid >> 5] = mx;
    __syncthreads();
    mx = smx[0];
#pragma unroll
    for (int i = 1; i < 8; i++) mx = fmaxf(mx, smx[i]);

    x.x = expf(x.x - mx);
    x.y = expf(x.y - mx);
    x.z = expf(x.z - mx);
    x.w = expf(x.w - mx);

    float s = x.x + x.y + x.z + x.w;
#pragma unroll
    for (int o = 16; o; o >>= 1) s += __shfl_xor_sync(0xffffffffu, s, o);
    if ((tid & 31) == 0) ssum[tid >> 5] = s;
    __syncthreads();
    s = ssum[0];
#pragma unroll
    for (int i = 1; i < 8; i++) s += ssum[i];

    const float inv = 1.0f / s;
    x.x *= inv; x.y *= inv; x.z *= inv; x.w *= inv;
    *(float4*)(p + tid * 4) = x;
}

// ---------------------------------------------------------------------------
// Launch: inputs in metadata order q,k,v,Wq,bq,Wk,bk,Wv,bv,Wo,bo
// ---------------------------------------------------------------------------
extern "C" void kernel_launch(void* const* d_in, const int* in_sizes, int n_in,
                              void* d_out, int out_size) {
    const float* q  = (const float*)d_in[0];
    const float* k  = (const float*)d_in[1];
    const float* v  = (const float*)d_in[2];
    const float* Wq = (const float*)d_in[3];
    const float* bq = (const float*)d_in[4];
    const float* Wk = (const float*)d_in[5];
    const float* bk = (const float*)d_in[6];
    const float* Wv = (const float*)d_in[7];
    const float* bv = (const float*)d_in[8];
    const float* Wo = (const float*)d_in[9];
    const float* bo = (const float*)d_in[10];
    float* out = (float*)d_out;

    pe_init_kernel<<<256, 256>>>();

    gemm_kernel<0><<<dim3(32, 16, 1),  256>>>(q, Wq, nullptr, bq);
    gemm_kernel<1><<<dim3(32, 16, 1),  256>>>(k, Wk, nullptr, bk);
    gemm_kernel<2><<<dim3(32, 16, 1),  256>>>(v, Wv, nullptr, bv);
    gemm_kernel<3><<<dim3(8, 16, 64),  256>>>(nullptr, nullptr, nullptr, nullptr);
    softmax_kernel<<<BH * SEQ, 256>>>();
    gemm_kernel<4><<<dim3(8, 1, 64),   256>>>(nullptr, nullptr, nullptr, nullptr);
    gemm_kernel<5><<<dim3(32, 16, 1),  256>>>(nullptr, Wo, out, bo);
}